// round 2
// baseline (speedup 1.0000x reference)
#include <cuda_runtime.h>

#define PRED_TILE 256
#define M_CHUNK   1024

__global__ void pdl_zero(float* __restrict__ out, int n) {
    int i = blockIdx.x * blockDim.x + threadIdx.x;
    if (i < n) out[i] = 0.0f;
}

__global__ __launch_bounds__(PRED_TILE)
void pdl_kernel(const float* __restrict__ pred,
                const float* __restrict__ targ,
                float* __restrict__ out, int N) {
    __shared__ float4 sh[M_CHUNK];
    __shared__ float warpsum[PRED_TILE / 32];

    const int b        = blockIdx.z;
    const int predIdx  = b * N + blockIdx.x * PRED_TILE + threadIdx.x;
    const int mBase    = b * N + blockIdx.y * M_CHUNK;

    // Cooperative load of the target chunk: {tx, ty, tz, |t|^2}
    for (int i = threadIdx.x; i < M_CHUNK; i += PRED_TILE) {
        const float* t = targ + (size_t)(mBase + i) * 3;
        float tx = t[0], ty = t[1], tz = t[2];
        sh[i] = make_float4(tx, ty, tz, fmaf(tx, tx, fmaf(ty, ty, tz * tz)));
    }

    // This thread's pred point
    const float* p = pred + (size_t)predIdx * 3;
    float px = p[0], py = p[1], pz = p[2];
    float ax = -2.0f * px, ay = -2.0f * py, az = -2.0f * pz;
    float p2 = fmaf(px, px, fmaf(py, py, pz * pz));

    __syncthreads();

    float acc = 0.0f;
#pragma unroll 8
    for (int m = 0; m < M_CHUNK; ++m) {
        float4 t = sh[m];                 // LDS.128 broadcast (same addr across warp)
        float s = p2 + t.w;
        s = fmaf(ax, t.x, s);
        s = fmaf(ay, t.y, s);
        s = fmaf(az, t.z, s);
        s = fmaxf(s, 0.0f);               // guard against negative cancellation -> NaN
        float d;
        asm("sqrt.approx.f32 %0, %1;" : "=f"(d) : "f"(s));  // force MUFU.SQRT
        acc += d;
    }

    // Intra-warp reduce
#pragma unroll
    for (int o = 16; o > 0; o >>= 1)
        acc += __shfl_down_sync(0xffffffffu, acc, o);
    if ((threadIdx.x & 31) == 0) warpsum[threadIdx.x >> 5] = acc;
    __syncthreads();

    // First warp reduces the 8 warp partials
    if (threadIdx.x < PRED_TILE / 32) {
        float v = warpsum[threadIdx.x];
#pragma unroll
        for (int o = PRED_TILE / 64; o > 0; o >>= 1)
            v += __shfl_down_sync(0x000000ffu, v, o);
        if (threadIdx.x == 0) {
            float scale = 1.0f / ((float)N * (float)N);
            atomicAdd(&out[b], v * scale);
        }
    }
}

extern "C" void kernel_launch(void* const* d_in, const int* in_sizes, int n_in,
                              void* d_out, int out_size) {
    const float* pred = (const float*)d_in[0];
    const float* targ = (const float*)d_in[1];
    float* out = (float*)d_out;

    const int B = out_size;                       // 4
    const int N = in_sizes[0] / (3 * B);          // 8192

    pdl_zero<<<1, 32>>>(out, B);

    dim3 grid(N / PRED_TILE, N / M_CHUNK, B);     // (32, 8, 4)
    pdl_kernel<<<grid, PRED_TILE>>>(pred, targ, out, N);
}